// round 14
// baseline (speedup 1.0000x reference)
#include <cuda_runtime.h>
#include <cstdint>

// out[b, 0:128]   = x[b, :]                       for b < B
// out[b, 128:256] = sum_{e: dst[e]==b} x[src[e]]
//
// Pipeline (2 graph nodes, PDL-overlapped):
//   K1 bin+copy, ROLE-SPLIT BY BLOCK:
//       blocks [0, BIN_BLOCKS):  edge binning only (atomic chains).
//       blocks [BIN_BLOCKS, ..): pure streaming copy out[b,0:128]=x[b]
//                                (no atomics in the instruction stream ->
//                                full stream efficiency, concurrent with
//                                the latency-idle bin blocks).
//   K2 main: PDL-dependent; untouchable gather loop (any store BEFORE it
//            destroys ptxas load batching — measured 3x). Writes only the
//            second half. Trailing self-cleans replace all memsets.

#define NFEAT   128
#define ROW_OUT 256
#define MAX_E   640000
#define B_MAX   65536
#define SLOTS   32

__device__ int  g_cnt[B_MAX];
__device__ int  g_ell[B_MAX * SLOTS];
__device__ int2 g_ovf[MAX_E];
__device__ int  g_ovf_count;

__global__ void bin_copy_kernel(const int* __restrict__ ei,
                                const float* __restrict__ x,
                                float* __restrict__ out,
                                int E, int B, int bin_blocks) {
    int tid = threadIdx.x;

    if ((int)blockIdx.x < bin_blocks) {
        // ---- Binning role: one edge per thread ----
        int i = blockIdx.x * blockDim.x + tid;
        if (i < E) {
            int d = __ldg(ei + E + i);
            if ((unsigned)d < (unsigned)B) {
                int s = __ldg(ei + i);
                int k = atomicAdd(&g_cnt[d], 1);
                if (k < SLOTS) {
                    g_ell[d * SLOTS + k] = s;
                } else {
                    int p = atomicAdd(&g_ovf_count, 1);
                    g_ovf[p] = make_int2(s, d);
                }
            }
        }
    } else {
        // ---- Copy role: pure stream, out[b,0:128] = x[b,:] ----
        int cb = blockIdx.x - bin_blocks;
        int nthreads = (gridDim.x - bin_blocks) * blockDim.x;
        int nq = B * (NFEAT / 4);
        for (int q = cb * blockDim.x + tid; q < nq; q += nthreads) {
            int row = q >> 5;            // 32 float4s per x row
            int c4  = q & 31;
            float4 v = __ldg(reinterpret_cast<const float4*>(
                                 x + (size_t)row * NFEAT) + c4);
            reinterpret_cast<float4*>(out + (size_t)row * ROW_OUT)[c4] = v;
        }
    }

    // Allow the dependent main_kernel to begin; its
    // cudaGridDependencySynchronize orders against all stores above.
    cudaTriggerProgrammaticLaunchCompletion();
}

__global__ void main_kernel(const float* __restrict__ x,
                            float* __restrict__ out,
                            int B) {
    cudaGridDependencySynchronize();

    int warp = (blockIdx.x * blockDim.x + threadIdx.x) >> 5;
    int lane = threadIdx.x & 31;
    if (warp >= B) return;
    int b = warp;

    int c_raw = g_cnt[b];
    int c = c_raw < SLOTS ? c_raw : SLOTS;

    // Coalesced preload of this row's source list (one slot per lane).
    int src_l = (lane < c) ? g_ell[b * SLOTS + lane] : 0;

    float4 acc = make_float4(0.f, 0.f, 0.f, 0.f);
    for (int k = 0; k < c; k++) {
        int se = __shfl_sync(0xFFFFFFFFu, src_l, k);
        float4 v = __ldg(reinterpret_cast<const float4*>(
                             x + (size_t)se * NFEAT) + lane);
        acc.x += v.x; acc.y += v.y; acc.z += v.z; acc.w += v.w;
    }

    // Rare path: degree exceeded SLOTS -> extras live in the overflow list.
    if (c_raw > SLOTS) {
        int n = g_ovf_count;
        for (int e = 0; e < n; e++) {
            int2 ed = g_ovf[e];
            if (ed.y == b) {
                float4 v = __ldg(reinterpret_cast<const float4*>(
                                     x + (size_t)ed.x * NFEAT) + lane);
                acc.x += v.x; acc.y += v.y; acc.z += v.z; acc.w += v.w;
            }
        }
    }

    // Second half only (first half written by the copy-role blocks of K1).
    float4* orow = reinterpret_cast<float4*>(out + (size_t)b * ROW_OUT);
    orow[(NFEAT / 4) + lane] = acc;

    // Trailing self-clean (measured benign): restores counters for the
    // next graph replay; no memset nodes needed.
    if (lane == 0) g_cnt[b] = 0;
    if (b == 0 && lane == 0) g_ovf_count = 0;
}

extern "C" void kernel_launch(void* const* d_in, const int* in_sizes, int n_in,
                              void* d_out, int out_size) {
    const float* x        = (const float*)d_in[0];
    const int*   edge_idx = (const int*)d_in[1];
    float*       out      = (float*)d_out;

    int B = out_size / ROW_OUT;          // 50000
    int E = in_sizes[1] / 2;             // 640000

    {   // K1: binning blocks + copy blocks in one launch
        int threads = 256;
        int bin_blocks  = (E + threads - 1) / threads;            // 2500
        int nq          = B * (NFEAT / 4);                        // 1.6M
        int copy_blocks = (nq + threads * 4 - 1) / (threads * 4); // ~4 quads/thr
        bin_copy_kernel<<<bin_blocks + copy_blocks, threads>>>(
            edge_idx, x, out, E, B, bin_blocks);
    }
    {   // K2: main gather-accumulate, PDL-overlapped with K1's tail
        int threads = 256;                          // 8 warps/block
        int blocks = (B + 7) / 8;

        cudaLaunchConfig_t cfg = {};
        cfg.gridDim  = dim3(blocks, 1, 1);
        cfg.blockDim = dim3(threads, 1, 1);
        cfg.dynamicSmemBytes = 0;
        cfg.stream = 0;
        cudaLaunchAttribute attrs[1];
        attrs[0].id = cudaLaunchAttributeProgrammaticStreamSerialization;
        attrs[0].val.programmaticStreamSerializationAllowed = 1;
        cfg.attrs = attrs;
        cfg.numAttrs = 1;
        cudaLaunchKernelEx(&cfg, main_kernel, x, out, B);
    }
}

// round 15
// speedup vs baseline: 1.0471x; 1.0471x over previous
#include <cuda_runtime.h>
#include <cstdint>

// out[b, 0:128]   = x[b, :]                       for b < B
// out[b, 128:256] = sum_{e: dst[e]==b} x[src[e]]
//
// Pipeline (3 graph nodes, PDL-chained for concurrency):
//   K0 copy: out[b,0:128]=x[b]; PDL trigger AT ENTRY (single-wave grid) so
//            K1 launches immediately and runs CONCURRENTLY with the copy.
//   K1 bin:  ELL binning; reads nothing from K0 -> skips grid sync; trigger
//            at end for K2's ramp overlap.
//   K2 main: grid sync (needs bin's data only; copy writes a disjoint
//            region and is ordered before graph completion by the stream).
//            Untouchable gather loop (any store BEFORE it destroys ptxas
//            load batching — measured 3x). Trailing self-cleans.

#define NFEAT   128
#define ROW_OUT 256
#define MAX_E   640000
#define B_MAX   65536
#define SLOTS   32

__device__ int  g_cnt[B_MAX];
__device__ int  g_ell[B_MAX * SLOTS];
__device__ int2 g_ovf[MAX_E];
__device__ int  g_ovf_count;

__global__ void copy_kernel(const float* __restrict__ x,
                            float* __restrict__ out,
                            int B) {
    // Fire first: grid is single-wave, so this releases K1 immediately.
    cudaTriggerProgrammaticLaunchCompletion();

    int i = blockIdx.x * blockDim.x + threadIdx.x;
    int nthreads = gridDim.x * blockDim.x;
    int nq = B * (NFEAT / 4);
    for (int q = i; q < nq; q += nthreads) {
        int row = q >> 5;            // 32 float4s per x row
        int c4  = q & 31;
        float4 v = __ldg(reinterpret_cast<const float4*>(
                             x + (size_t)row * NFEAT) + c4);
        reinterpret_cast<float4*>(out + (size_t)row * ROW_OUT)[c4] = v;
    }
}

__global__ void bin_kernel(const int* __restrict__ ei, int E, int B) {
    // No cudaGridDependencySynchronize: reads nothing written by copy_kernel.
    int i = blockIdx.x * blockDim.x + threadIdx.x;
    if (i < E) {
        int d = __ldg(ei + E + i);
        if ((unsigned)d < (unsigned)B) {
            int s = __ldg(ei + i);
            int k = atomicAdd(&g_cnt[d], 1);
            if (k < SLOTS) {
                g_ell[d * SLOTS + k] = s;
            } else {
                int p = atomicAdd(&g_ovf_count, 1);
                g_ovf[p] = make_int2(s, d);
            }
        }
    }
    cudaTriggerProgrammaticLaunchCompletion();
}

__global__ void main_kernel(const float* __restrict__ x,
                            float* __restrict__ out,
                            int B) {
    cudaGridDependencySynchronize();

    int warp = (blockIdx.x * blockDim.x + threadIdx.x) >> 5;
    int lane = threadIdx.x & 31;
    if (warp >= B) return;
    int b = warp;

    int c_raw = g_cnt[b];
    int c = c_raw < SLOTS ? c_raw : SLOTS;

    // Coalesced preload of this row's source list (one slot per lane).
    int src_l = (lane < c) ? g_ell[b * SLOTS + lane] : 0;

    float4 acc = make_float4(0.f, 0.f, 0.f, 0.f);
    for (int k = 0; k < c; k++) {
        int se = __shfl_sync(0xFFFFFFFFu, src_l, k);
        float4 v = __ldg(reinterpret_cast<const float4*>(
                             x + (size_t)se * NFEAT) + lane);
        acc.x += v.x; acc.y += v.y; acc.z += v.z; acc.w += v.w;
    }

    // Rare path: degree exceeded SLOTS -> extras live in the overflow list.
    if (c_raw > SLOTS) {
        int n = g_ovf_count;
        for (int e = 0; e < n; e++) {
            int2 ed = g_ovf[e];
            if (ed.y == b) {
                float4 v = __ldg(reinterpret_cast<const float4*>(
                                     x + (size_t)ed.x * NFEAT) + lane);
                acc.x += v.x; acc.y += v.y; acc.z += v.z; acc.w += v.w;
            }
        }
    }

    // Second half only (first half written by copy_kernel).
    float4* orow = reinterpret_cast<float4*>(out + (size_t)b * ROW_OUT);
    orow[(NFEAT / 4) + lane] = acc;

    // Trailing self-clean (measured benign): restores counters for the
    // next graph replay; no memset nodes needed.
    if (lane == 0) g_cnt[b] = 0;
    if (b == 0 && lane == 0) g_ovf_count = 0;
}

extern "C" void kernel_launch(void* const* d_in, const int* in_sizes, int n_in,
                              void* d_out, int out_size) {
    const float* x        = (const float*)d_in[0];
    const int*   edge_idx = (const int*)d_in[1];
    float*       out      = (float*)d_out;

    int B = out_size / ROW_OUT;          // 50000
    int E = in_sizes[1] / 2;             // 640000

    {   // K0: first-half copy; single-wave grid, entry trigger
        copy_kernel<<<1024, 256>>>(x, out, B);
    }
    {   // K1: binning, PDL-overlapped with the copy's body
        int threads = 256;
        int blocks = (E + threads - 1) / threads;
        cudaLaunchConfig_t cfg = {};
        cfg.gridDim  = dim3(blocks, 1, 1);
        cfg.blockDim = dim3(threads, 1, 1);
        cfg.stream = 0;
        cudaLaunchAttribute attrs[1];
        attrs[0].id = cudaLaunchAttributeProgrammaticStreamSerialization;
        attrs[0].val.programmaticStreamSerializationAllowed = 1;
        cfg.attrs = attrs;
        cfg.numAttrs = 1;
        cudaLaunchKernelEx(&cfg, bin_kernel, edge_idx, E, B);
    }
    {   // K2: main gather-accumulate, PDL-overlapped with bin's tail
        int threads = 256;                          // 8 warps/block
        int blocks = (B + 7) / 8;
        cudaLaunchConfig_t cfg = {};
        cfg.gridDim  = dim3(blocks, 1, 1);
        cfg.blockDim = dim3(threads, 1, 1);
        cfg.stream = 0;
        cudaLaunchAttribute attrs[1];
        attrs[0].id = cudaLaunchAttributeProgrammaticStreamSerialization;
        attrs[0].val.programmaticStreamSerializationAllowed = 1;
        cfg.attrs = attrs;
        cfg.numAttrs = 1;
        cudaLaunchKernelEx(&cfg, main_kernel, x, out, B);
    }
}